// round 17
// baseline (speedup 1.0000x reference)
#include <cuda_runtime.h>
#include <cstdint>

// SyntheticTripletLoss closed form: per valid row only
//   pp=<p,p>, tt=<t,t>, pt=<p,t>
//   sim_pn = (pp - pt^2) / max(sqrt(pp - 2pt^2 + pt^2*tt), EPS)
//   loss   = max(MARGIN + sim_pn - pt, 0); mean over valid rows.
//
// R17 = R16 (register-only balanced mapper + single packed-u64 atomic tail)
// with 256-bit streaming loads (4x v8.b32 per lane instead of 8x LDG.128):
// half the LSU issue slots per warp, same bytes. The kernel is at the LTS
// B/cyc cap for the chip's idle clock (33.6MB / 6300 B/cyc == measured
// duration); this trims the remaining issue-side ramp/drain.

#define MARGIN 0.5f
#define EPS_N 1e-12f

static constexpr int B = 32;
static constexpr int T = 512;
static constexpr int D = 512;
static constexpr int WARPS_PER_BLOCK = 8;
static constexpr int THREADS = WARPS_PER_BLOCK * 32;    // 256
static constexpr int ROWS = B * T;                      // 16384
static constexpr int NBLOCKS = ROWS / WARPS_PER_BLOCK;  // 2048 (worst case)

static constexpr double FIX_SCALE = 16777216.0;         // 2^24
static constexpr int CNT_SHIFT = 50;

__device__ unsigned long long g_acc;   // zero-init; last block resets each run

// 256-bit non-coherent global load.
__device__ __forceinline__ void ldg256(const float* p, float* v) {
    uint32_t r0, r1, r2, r3, r4, r5, r6, r7;
    asm volatile(
        "ld.global.nc.L2::evict_last.v8.b32 {%0,%1,%2,%3,%4,%5,%6,%7}, [%8];"
        : "=r"(r0), "=r"(r1), "=r"(r2), "=r"(r3),
          "=r"(r4), "=r"(r5), "=r"(r6), "=r"(r7)
        : "l"(p));
    v[0] = __uint_as_float(r0); v[1] = __uint_as_float(r1);
    v[2] = __uint_as_float(r2); v[3] = __uint_as_float(r3);
    v[4] = __uint_as_float(r4); v[5] = __uint_as_float(r5);
    v[6] = __uint_as_float(r6); v[7] = __uint_as_float(r7);
}

__global__ __launch_bounds__(THREADS)
void triplet_cap_kernel(const float* __restrict__ preds,
                        const float* __restrict__ targets,
                        const int* __restrict__ lengths,
                        float* __restrict__ out) {
    const int warp = threadIdx.x >> 5;
    const int lane = threadIdx.x & 31;

    // ---- warp-private scan of lengths (register-only, no smem/sync) ----
    const int len = __ldg(&lengths[lane]);   // L2-hot after first wave
    int inc = len;
    #pragma unroll
    for (int off = 1; off < 32; off <<= 1) {
        int n = __shfl_up_sync(0xffffffffu, inc, off);
        if (lane >= off) inc += n;
    }
    const int total = __shfl_sync(0xffffffffu, inc, 31);
    const int excl  = inc - len;             // exclusive prefix at this lane

    const int vid = blockIdx.x * WARPS_PER_BLOCK + warp;

    float loss = 0.0f;

    if (vid < total) {
        // b = largest lane with excl <= vid (excl nondecreasing).
        unsigned int mask = __ballot_sync(0xffffffffu, excl <= vid);
        const int bsel = 31 - __clz(mask);
        const int base = __shfl_sync(0xffffffffu, excl, bsel);
        const int row  = bsel * T + (vid - base);

        const float* __restrict__ pr = preds   + (size_t)row * D;
        const float* __restrict__ tr = targets + (size_t)row * D;

        // 512 floats / 32 lanes = 16 floats = 2 v8 per tensor per lane;
        // 4 LDG instructions total, front-batched.
        float a[16], c[16];
        ldg256(pr + lane * 8, a);
        ldg256(pr + 256 + lane * 8, a + 8);
        ldg256(tr + lane * 8, c);
        ldg256(tr + 256 + lane * 8, c + 8);

        float pp = 0.f, tt = 0.f, pt = 0.f;
        #pragma unroll
        for (int i = 0; i < 16; i++) {
            pp = fmaf(a[i], a[i], pp);
            tt = fmaf(c[i], c[i], tt);
            pt = fmaf(a[i], c[i], pt);
        }

        #pragma unroll
        for (int off = 16; off; off >>= 1) {
            pp += __shfl_xor_sync(0xffffffffu, pp, off);
            tt += __shfl_xor_sync(0xffffffffu, tt, off);
            pt += __shfl_xor_sync(0xffffffffu, pt, off);
        }

        float pt2  = pt * pt;
        float n2   = fmaxf(pp - 2.0f * pt2 + pt2 * tt, 0.0f);
        float norm = fmaxf(sqrtf(n2), EPS_N);
        loss = fmaxf(MARGIN + (pp - pt2) / norm - pt, 0.0f);
    }

    // ---- block sum (smem + warp-0 shuffle) -> single packed atomic ----
    __shared__ float s_warp[WARPS_PER_BLOCK];
    if (lane == 0) s_warp[warp] = loss;
    __syncthreads();

    if (warp == 0) {
        float sum = (lane < WARPS_PER_BLOCK) ? s_warp[lane] : 0.0f;
        #pragma unroll
        for (int off = 4; off; off >>= 1)
            sum += __shfl_xor_sync(0xffffffffu, sum, off);

        if (lane == 0) {
            // 2^24 fixed point via double (exact in this range); loss >= 0.
            // Overflow audit: block sum <= ~1e3 -> <=2^34 fixed; 2048 blocks
            // -> <=2^45 < 2^50. Count: 2048 * 2^50 = 2^61 < 2^64.
            unsigned long long contrib =
                (unsigned long long)((double)sum * FIX_SCALE);
            unsigned long long packed = (1ULL << CNT_SHIFT) + contrib;

            unsigned long long old = atomicAdd(&g_acc, packed);

            if ((old >> CNT_SHIFT) == (unsigned long long)(NBLOCKS - 1)) {
                // Last block: chip total is in the atomic's return value.
                unsigned long long total_fix =
                    (old + packed) & ((1ULL << CNT_SHIFT) - 1ULL);
                out[0] = (float)((double)total_fix / FIX_SCALE /
                                 (double)total);
                g_acc = 0;   // reset for next graph replay (all other
                             // blocks' atomics preceded ours)
            }
        }
    }
}

extern "C" void kernel_launch(void* const* d_in, const int* in_sizes, int n_in,
                              void* d_out, int out_size) {
    const float* preds   = (const float*)d_in[0];
    const float* targets = (const float*)d_in[1];
    const int*   lengths = (const int*)d_in[2];
    float* out = (float*)d_out;

    triplet_cap_kernel<<<NBLOCKS, THREADS>>>(preds, targets, lengths, out);
}